// round 1
// baseline (speedup 1.0000x reference)
#include <cuda_runtime.h>
#include <math.h>

// ---------------------------------------------------------------------------
// DetectionFocalLoss: fused anchor-assignment + focal cls loss + smooth-L1 reg
// B=8, N=100000, C=80 (hardcoded), M=32.
//
// Kernel 1 (grid = (ceil(N/256), B), 256 thr):
//   phase 0: load+precompute 32 annotations into SMEM
//   phase 1: 1 anchor/thread: IoU vs 32 anns -> status (pos/neg/ignore),
//            assigned class; pos anchors also compute smooth-L1 reg terms.
//   phase 2: coalesced float4 sweep of the 256x80 classification tile,
//            focal term = (-alpha*ln2)*(1-x)^2*log2(x), x = one? p : 1-p.
//   block-reduce (cls_sum, reg_sum, pos_cnt) -> per-block partial slots.
// Kernel 2: deterministic tree reduction of partials, final 2 scalars.
// ---------------------------------------------------------------------------

#define AANCH   256     // anchors per block
#define THREADS 256
#define CQ      20      // C/4 = 80/4 float4 per anchor
#define CNUM    80
#define MAXM    64
#define MAXBLK  16384

__device__ float g_cls[MAXBLK];
__device__ float g_reg[MAXBLK];
__device__ float g_pos[MAXBLK];

__device__ __forceinline__ float smooth_l1(float d) {
    return (d < 1.0f) ? 0.5f * d * d : d - 0.5f;
}

__global__ void __launch_bounds__(THREADS)
focal_main_kernel(const float* __restrict__ cls,
                  const float* __restrict__ reg,
                  const float* __restrict__ anchors,
                  const float* __restrict__ ann,
                  int N, int M, int gridX)
{
    __shared__ float sbx1[MAXM], sby1[MAXM], sbx2[MAXM], sby2[MAXM];
    __shared__ float sarea[MAXM], sbw[MAXM], sbh[MAXM], sbdx[MAXM], sbdy[MAXM];
    __shared__ int   scid[MAXM];
    __shared__ int   s_info[AANCH];     // >=0: match-class (0xFFFF = neg, never matches); <0: ignore/invalid
    __shared__ float rc[8], rr[8], rp[8];

    const int tid = threadIdx.x;
    const int b   = blockIdx.y;

    // ---- phase 0: annotations -> SMEM ----
    if (tid < M) {
        const float* a5 = ann + ((size_t)b * M + tid) * 5;
        float x1 = a5[0], y1 = a5[1], x2 = a5[2], y2 = a5[3];
        sbx1[tid] = x1; sby1[tid] = y1; sbx2[tid] = x2; sby2[tid] = y2;
        sarea[tid] = (x2 - x1) * (y2 - y1);
        sbw[tid]  = x2 - x1;
        sbh[tid]  = y2 - y1;
        sbdx[tid] = x1 + x2 * 0.5f;   // matches reference: ag[:,0] + ag[:,2]/2
        sbdy[tid] = y1 + y2 * 0.5f;
        scid[tid] = (int)a5[4];
    }
    __syncthreads();

    // ---- phase 1: per-anchor assignment + regression loss ----
    float my_reg = 0.0f;
    float my_pos = 0.0f;
    {
        int a = tid;                       // AANCH == THREADS
        int i = blockIdx.x * AANCH + a;
        int info = (int)0x80000000;        // ignore / invalid
        if (i < N) {
            float4 an = ((const float4*)anchors)[i];   // cx, cy, w, h
            float cx = an.x, cy = an.y, w = an.z, h = an.w;
            float ax1 = cx - w * 0.5f, ay1 = cy - h * 0.5f;
            float ax2 = cx + w * 0.5f, ay2 = cy + h * 0.5f;
            float area_a = (ax2 - ax1) * (ay2 - ay1);

            float best = -1.0f;
            int   bm   = 0;
            for (int m = 0; m < M; m++) {
                float ltx = fmaxf(ax1, sbx1[m]);
                float lty = fmaxf(ay1, sby1[m]);
                float rbx = fminf(ax2, sbx2[m]);
                float rby = fminf(ay2, sby2[m]);
                float wx = fmaxf(rbx - ltx, 0.0f);
                float wy = fmaxf(rby - lty, 0.0f);
                float inter = wx * wy;
                float uni = area_a + sarea[m] - inter;
                float iou = inter / fmaxf(uni, 1e-8f);
                if (iou > best) { best = iou; bm = m; }   // first-max (argmax)
            }

            if (best >= 0.5f) {
                info = scid[bm];
                // regression smooth-L1
                float4 r = ((const float4*)reg)[(size_t)b * N + i];
                float dx  = (sbdx[bm] - cx) / w;
                float dy  = (sbdy[bm] - cy) / h;
                float dwl = __logf(sbw[bm] / w);
                float dhl = __logf(sbh[bm] / h);
                float d0 = fabsf(r.x - dx)  * 10.0f;   // /0.1
                float d1 = fabsf(r.y - dy)  * 10.0f;   // /0.1
                float d2 = fabsf(r.z - dwl) * 5.0f;    // /0.2
                float d3 = fabsf(r.w - dhl) * 5.0f;    // /0.2
                my_reg = smooth_l1(d0) + smooth_l1(d1) + smooth_l1(d2) + smooth_l1(d3);
                my_pos = 1.0f;
            } else if (best <= 0.4f) {
                info = 0xFFFF;             // negative anchor: no class matches
            }
            // else: ignore (info stays negative)
        }
        s_info[a] = info;
    }
    __syncthreads();

    // ---- phase 2: classification sweep (coalesced float4) ----
    const float EPS = 1e-4f;
    const float HI  = 1.0f - 1e-4f;
    const float K1  = -0.25f * 0.69314718055994531f;   // alpha * ln2, sign-folded
    const float K0  = -0.75f * 0.69314718055994531f;

    float my_cls = 0.0f;
    {
        const float4* cp = (const float4*)cls
                         + ((size_t)b * N + (size_t)blockIdx.x * AANCH) * CQ;
        #pragma unroll 4
        for (int v = tid; v < AANCH * CQ; v += THREADS) {
            int av  = v / CQ;
            int inf = s_info[av];
            if (inf >= 0) {
                float4 p4 = cp[v];
                int c0 = (v - av * CQ) * 4;
                float pv[4] = {p4.x, p4.y, p4.z, p4.w};
                #pragma unroll
                for (int j = 0; j < 4; j++) {
                    bool one = ((c0 + j) == inf);
                    float x = one ? pv[j] : 1.0f - pv[j];
                    x = fminf(fmaxf(x, EPS), HI);
                    float omx = 1.0f - x;
                    float k = one ? K1 : K0;
                    my_cls = fmaf(k * omx * omx, __log2f(x), my_cls);
                }
            }
        }
    }

    // ---- block reduce (deterministic) ----
    unsigned full = 0xFFFFFFFFu;
    #pragma unroll
    for (int off = 16; off > 0; off >>= 1) {
        my_cls += __shfl_down_sync(full, my_cls, off);
        my_reg += __shfl_down_sync(full, my_reg, off);
        my_pos += __shfl_down_sync(full, my_pos, off);
    }
    int wid = tid >> 5, lane = tid & 31;
    if (lane == 0) { rc[wid] = my_cls; rr[wid] = my_reg; rp[wid] = my_pos; }
    __syncthreads();
    if (tid == 0) {
        float c = 0.f, r = 0.f, p = 0.f;
        #pragma unroll
        for (int w = 0; w < THREADS / 32; w++) { c += rc[w]; r += rr[w]; p += rp[w]; }
        int slot = b * gridX + blockIdx.x;
        g_cls[slot] = c;
        g_reg[slot] = r;
        g_pos[slot] = p;
    }
}

__global__ void __launch_bounds__(256)
focal_finalize_kernel(float* __restrict__ out, int gridX, int B)
{
    __shared__ float sc[256], sr[256], sp[256];
    const int tid = threadIdx.x;
    float a_cls = 0.f, a_es = 0.f, a_ec = 0.f;   // only thread 0's copies matter

    for (int b = 0; b < B; b++) {
        float c = 0.f, r = 0.f, p = 0.f;
        for (int x = tid; x < gridX; x += 256) {
            int s = b * gridX + x;
            c += g_cls[s]; r += g_reg[s]; p += g_pos[s];
        }
        sc[tid] = c; sr[tid] = r; sp[tid] = p;
        __syncthreads();
        for (int s = 128; s > 0; s >>= 1) {
            if (tid < s) { sc[tid] += sc[tid + s]; sr[tid] += sr[tid + s]; sp[tid] += sp[tid + s]; }
            __syncthreads();
        }
        if (tid == 0) {
            float pos   = sp[0];
            float denom = fmaxf(pos, 1.0f);
            a_cls += sc[0] / denom;
            if (pos > 0.0f) {
                float rm = sr[0] / (denom * 4.0f);
                a_es += rm / denom + rm;
                a_ec += 2.0f;
            } else {
                a_ec += 1.0f;
            }
        }
        __syncthreads();
    }
    if (tid == 0) {
        out[0] = a_cls / (float)B;
        out[1] = a_es / a_ec;
    }
}

extern "C" void kernel_launch(void* const* d_in, const int* in_sizes, int n_in,
                              void* d_out, int out_size)
{
    const float* cls     = (const float*)d_in[0];   // (B, N, 80)
    const float* reg     = (const float*)d_in[1];   // (B, N, 4)
    const float* anchors = (const float*)d_in[2];   // (1, N, 4)
    const float* ann     = (const float*)d_in[3];   // (B, M, 5)

    int N = in_sizes[2] / 4;
    int B = in_sizes[1] / (4 * N);
    int M = in_sizes[3] / (5 * B);
    if (M > MAXM) M = MAXM;

    int gridX = (N + AANCH - 1) / AANCH;
    dim3 grid(gridX, B);
    focal_main_kernel<<<grid, THREADS>>>(cls, reg, anchors, ann, N, M, gridX);
    focal_finalize_kernel<<<1, 256>>>((float*)d_out, gridX, B);
}

// round 2
// speedup vs baseline: 1.1105x; 1.1105x over previous
#include <cuda_runtime.h>
#include <math.h>

// ---------------------------------------------------------------------------
// DetectionFocalLoss (B=8, N=100000, C=80, M=32)
// Kernel 1: fused assignment + focal-cls + smooth-L1 partials per block.
//   phase 2 mapping: thread t -> anchor (t>>2), col-group (t&3);
//   5 independent float4 loads per (thread, chunk); warp-uniform negative path.
// Kernel 2: one warp per batch, shuffle reduce -> final 2 scalars.
// ---------------------------------------------------------------------------

#define AANCH   256
#define THREADS 256
#define CQ      20          // 80/4 float4 per anchor row
#define MAXM    64
#define MAXBLK  16384
#define NEGCODE 1000        // negative anchor: never equals a class id
// info: 0..79 = positive (class id); NEGCODE = negative; <0 = ignore/invalid

__device__ float g_cls[MAXBLK];
__device__ float g_reg[MAXBLK];
__device__ float g_pos[MAXBLK];

__device__ __forceinline__ float smooth_l1(float d) {
    return (d < 1.0f) ? 0.5f * d * d : d - 0.5f;
}

#define EPSC 1e-4f
#define HIC  (1.0f - 1e-4f)
#define K1C  (-0.25f * 0.69314718055994531f)
#define K0C  (-0.75f * 0.69314718055994531f)

// negative-anchor element: label 0, x = clamp(1-p)
__device__ __forceinline__ float neg_term(float p) {
    float x = fminf(fmaxf(1.0f - p, EPSC), HIC);
    float omx = 1.0f - x;
    return K0C * omx * omx * __log2f(x);
}

// positive-anchor element: label 1 iff class c == inf
__device__ __forceinline__ float pos_term(float p, int c, int inf) {
    bool one = (c == inf);
    float x = one ? p : 1.0f - p;
    x = fminf(fmaxf(x, EPSC), HIC);
    float omx = 1.0f - x;
    float k = one ? K1C : K0C;
    return k * omx * omx * __log2f(x);
}

__global__ void __launch_bounds__(THREADS)
focal_main_kernel(const float* __restrict__ cls,
                  const float* __restrict__ reg,
                  const float* __restrict__ anchors,
                  const float* __restrict__ ann,
                  int N, int M, int gridX)
{
    __shared__ float sbx1[MAXM], sby1[MAXM], sbx2[MAXM], sby2[MAXM];
    __shared__ float sarea[MAXM], sbw[MAXM], sbh[MAXM], sbdx[MAXM], sbdy[MAXM];
    __shared__ int   scid[MAXM];
    __shared__ int   s_info[AANCH];
    __shared__ float rc[8], rr[8], rp[8];

    const int tid = threadIdx.x;
    const int b   = blockIdx.y;

    // ---- phase 0: annotations -> SMEM ----
    if (tid < M) {
        const float* a5 = ann + ((size_t)b * M + tid) * 5;
        float x1 = a5[0], y1 = a5[1], x2 = a5[2], y2 = a5[3];
        sbx1[tid] = x1; sby1[tid] = y1; sbx2[tid] = x2; sby2[tid] = y2;
        sarea[tid] = (x2 - x1) * (y2 - y1);
        sbw[tid]  = x2 - x1;
        sbh[tid]  = y2 - y1;
        sbdx[tid] = x1 + x2 * 0.5f;
        sbdy[tid] = y1 + y2 * 0.5f;
        scid[tid] = (int)a5[4];
    }
    __syncthreads();

    // ---- phase 1: per-anchor assignment + regression ----
    float my_reg = 0.0f;
    float my_pos = 0.0f;
    {
        int i = blockIdx.x * AANCH + tid;
        int info = -1;
        if (i < N) {
            float4 an = ((const float4*)anchors)[i];
            float cx = an.x, cy = an.y, w = an.z, h = an.w;
            float ax1 = cx - w * 0.5f, ay1 = cy - h * 0.5f;
            float ax2 = cx + w * 0.5f, ay2 = cy + h * 0.5f;
            float area_a = (ax2 - ax1) * (ay2 - ay1);

            float best = -1.0f;
            int   bm   = 0;
            #pragma unroll 8
            for (int m = 0; m < M; m++) {
                float ltx = fmaxf(ax1, sbx1[m]);
                float lty = fmaxf(ay1, sby1[m]);
                float rbx = fminf(ax2, sbx2[m]);
                float rby = fminf(ay2, sby2[m]);
                float wx = fmaxf(rbx - ltx, 0.0f);
                float wy = fmaxf(rby - lty, 0.0f);
                float inter = wx * wy;
                float uni = area_a + sarea[m] - inter;
                float iou = inter / fmaxf(uni, 1e-8f);
                if (iou > best) { best = iou; bm = m; }
            }

            if (best >= 0.5f) {
                info = scid[bm];
                float4 r = ((const float4*)reg)[(size_t)b * N + i];
                float dx  = (sbdx[bm] - cx) / w;
                float dy  = (sbdy[bm] - cy) / h;
                float dwl = __logf(sbw[bm] / w);
                float dhl = __logf(sbh[bm] / h);
                float d0 = fabsf(r.x - dx)  * 10.0f;
                float d1 = fabsf(r.y - dy)  * 10.0f;
                float d2 = fabsf(r.z - dwl) * 5.0f;
                float d3 = fabsf(r.w - dhl) * 5.0f;
                my_reg = smooth_l1(d0) + smooth_l1(d1) + smooth_l1(d2) + smooth_l1(d3);
                my_pos = 1.0f;
            } else if (best <= 0.4f) {
                info = NEGCODE;
            }
        }
        s_info[tid] = info;
    }
    __syncthreads();

    // ---- phase 2: classification sweep ----
    // thread t: anchor row arow = t>>2 (+64*chunk), col-group sub = t&3.
    // Each chunk: 5 float4 loads at stride 4 (64B) from the anchor's row.
    float my_cls = 0.0f;
    {
        const int sub  = tid & 3;
        const int arow = tid >> 2;
        const float4* base = (const float4*)cls
                           + ((size_t)b * N + (size_t)blockIdx.x * AANCH) * CQ;
        #pragma unroll
        for (int chunk = 0; chunk < 4; chunk++) {
            int a = chunk * 64 + arow;
            int inf = s_info[a];
            if (inf < 0) continue;   // ignore / out-of-range anchors
            const float4* rowp = base + a * CQ + sub;
            float4 q0 = rowp[0];
            float4 q1 = rowp[4];
            float4 q2 = rowp[8];
            float4 q3 = rowp[12];
            float4 q4 = rowp[16];
            if (inf == NEGCODE) {
                // all labels 0 — straight-line fast path
                my_cls += neg_term(q0.x) + neg_term(q0.y) + neg_term(q0.z) + neg_term(q0.w);
                my_cls += neg_term(q1.x) + neg_term(q1.y) + neg_term(q1.z) + neg_term(q1.w);
                my_cls += neg_term(q2.x) + neg_term(q2.y) + neg_term(q2.z) + neg_term(q2.w);
                my_cls += neg_term(q3.x) + neg_term(q3.y) + neg_term(q3.z) + neg_term(q3.w);
                my_cls += neg_term(q4.x) + neg_term(q4.y) + neg_term(q4.z) + neg_term(q4.w);
            } else {
                int c0 = sub * 4;    // column of q0.x; q_k starts at c0 + 16k
                float4 qs[5] = {q0, q1, q2, q3, q4};
                #pragma unroll
                for (int k = 0; k < 5; k++) {
                    int c = c0 + 16 * k;
                    my_cls += pos_term(qs[k].x, c + 0, inf);
                    my_cls += pos_term(qs[k].y, c + 1, inf);
                    my_cls += pos_term(qs[k].z, c + 2, inf);
                    my_cls += pos_term(qs[k].w, c + 3, inf);
                }
            }
        }
    }

    // ---- block reduce ----
    unsigned full = 0xFFFFFFFFu;
    #pragma unroll
    for (int off = 16; off > 0; off >>= 1) {
        my_cls += __shfl_down_sync(full, my_cls, off);
        my_reg += __shfl_down_sync(full, my_reg, off);
        my_pos += __shfl_down_sync(full, my_pos, off);
    }
    int wid = tid >> 5, lane = tid & 31;
    if (lane == 0) { rc[wid] = my_cls; rr[wid] = my_reg; rp[wid] = my_pos; }
    __syncthreads();
    if (tid == 0) {
        float c = 0.f, r = 0.f, p = 0.f;
        #pragma unroll
        for (int w = 0; w < THREADS / 32; w++) { c += rc[w]; r += rr[w]; p += rp[w]; }
        int slot = b * gridX + blockIdx.x;
        g_cls[slot] = c;
        g_reg[slot] = r;
        g_pos[slot] = p;
    }
}

// One warp per batch; shuffle reduce; thread 0 combines.
__global__ void __launch_bounds__(256)
focal_finalize_kernel(float* __restrict__ out, int gridX, int B)
{
    __shared__ float sb_cls[32], sb_es[32], sb_ec[32];
    const int tid  = threadIdx.x;
    const int w    = tid >> 5;
    const int lane = tid & 31;

    if (tid < 32) { sb_cls[tid] = 0.f; sb_es[tid] = 0.f; sb_ec[tid] = 0.f; }
    __syncthreads();

    for (int b = w; b < B; b += 8) {
        float c = 0.f, r = 0.f, p = 0.f;
        const int s0 = b * gridX;
        for (int x = lane; x < gridX; x += 32) {
            c += g_cls[s0 + x];
            r += g_reg[s0 + x];
            p += g_pos[s0 + x];
        }
        unsigned full = 0xFFFFFFFFu;
        #pragma unroll
        for (int off = 16; off > 0; off >>= 1) {
            c += __shfl_down_sync(full, c, off);
            r += __shfl_down_sync(full, r, off);
            p += __shfl_down_sync(full, p, off);
        }
        if (lane == 0) {
            float denom = fmaxf(p, 1.0f);
            sb_cls[b] = c / denom;
            if (p > 0.0f) {
                float rm = r / (denom * 4.0f);
                sb_es[b] = rm / denom + rm;
                sb_ec[b] = 2.0f;
            } else {
                sb_ec[b] = 1.0f;
            }
        }
    }
    __syncthreads();
    if (tid == 0) {
        float a_cls = 0.f, a_es = 0.f, a_ec = 0.f;
        for (int b = 0; b < B; b++) { a_cls += sb_cls[b]; a_es += sb_es[b]; a_ec += sb_ec[b]; }
        out[0] = a_cls / (float)B;
        out[1] = a_es / a_ec;
    }
}

extern "C" void kernel_launch(void* const* d_in, const int* in_sizes, int n_in,
                              void* d_out, int out_size)
{
    const float* cls     = (const float*)d_in[0];
    const float* reg     = (const float*)d_in[1];
    const float* anchors = (const float*)d_in[2];
    const float* ann     = (const float*)d_in[3];

    int N = in_sizes[2] / 4;
    int B = in_sizes[1] / (4 * N);
    int M = in_sizes[3] / (5 * B);
    if (M > MAXM) M = MAXM;

    int gridX = (N + AANCH - 1) / AANCH;
    dim3 grid(gridX, B);
    focal_main_kernel<<<grid, THREADS>>>(cls, reg, anchors, ann, N, M, gridX);
    focal_finalize_kernel<<<1, 256>>>((float*)d_out, gridX, B);
}